// round 3
// baseline (speedup 1.0000x reference)
#include <cuda_runtime.h>
#include <math.h>

#define NTOK 4096
#define DIM 1024
#define HID 2732
#define HID_PAD 2736
#define NEXP 8
#define MAXM 4096

// Scratch (static __device__ per allocation rules): H buffer [E*MAXM rows][HID_PAD]
__device__ float g_H[(size_t)NEXP * MAXM * HID_PAD];
__device__ int   g_cnt[NEXP];
__device__ int   g_tok[NEXP * MAXM];
__device__ float g_w[NEXP * MAXM];

// ---------------------------------------------------------------------------
__global__ void zero_kernel(float* __restrict__ out) {
    int i = blockIdx.x * blockDim.x + threadIdx.x;
    if (i < NTOK * DIM) out[i] = 0.f;
    if (i < NEXP) g_cnt[i] = 0;
}

// ---------------------------------------------------------------------------
// One warp per token: scores = x . Wg[e], top-2, softmax, route.
__global__ void gate_kernel(const float* __restrict__ x,
                            const float* __restrict__ Wg) {
    int gtid = blockIdx.x * blockDim.x + threadIdx.x;
    int tok  = gtid >> 5;
    int lane = gtid & 31;
    if (tok >= NTOK) return;
    const float* xr = x + (size_t)tok * DIM;
    float s[NEXP];
#pragma unroll
    for (int e = 0; e < NEXP; e++) s[e] = 0.f;
    for (int k = lane; k < DIM; k += 32) {
        float xv = xr[k];
#pragma unroll
        for (int e = 0; e < NEXP; e++) s[e] += xv * Wg[e * DIM + k];
    }
#pragma unroll
    for (int e = 0; e < NEXP; e++) {
#pragma unroll
        for (int off = 16; off; off >>= 1)
            s[e] += __shfl_xor_sync(0xffffffffu, s[e], off);
    }
    if (lane == 0) {
        int e0 = 0;
#pragma unroll
        for (int e = 1; e < NEXP; e++) if (s[e] > s[e0]) e0 = e;
        int e1 = (e0 == 0) ? 1 : 0;
#pragma unroll
        for (int e = 0; e < NEXP; e++) if (e != e0 && s[e] > s[e1]) e1 = e;
        float p1 = __expf(s[e1] - s[e0]);
        float w0 = 1.f / (1.f + p1);
        float w1 = p1 * w0;
        int q0 = atomicAdd(&g_cnt[e0], 1);
        g_tok[e0 * MAXM + q0] = tok;  g_w[e0 * MAXM + q0] = w0;
        int q1 = atomicAdd(&g_cnt[e1], 1);
        g_tok[e1 * MAXM + q1] = tok;  g_w[e1 * MAXM + q1] = w1;
    }
}

// ---------------------------------------------------------------------------
// Tiled SGEMM over gathered rows. BM=BN=128, BK=8, 256 threads, 8x8/thread.
// MODE 0: H1 = Xg @ W1^T              (store to g_H)
// MODE 1: H  = silu(H1) * (Xg @ W3^T) (read g_H, combine, store; zero pads)
// MODE 2: out[token] += w * (H @ W2^T) (atomicAdd)
template <int MODE>
__global__ void __launch_bounds__(256, 2)
gemm_kernel(const float* __restrict__ Xg,
            const float* __restrict__ Wbase,
            float* __restrict__ out) {
    const int e   = blockIdx.z;
    const int cnt = g_cnt[e];
    const int m0  = blockIdx.y * 128;
    if (m0 >= cnt) return;
    const int n0  = blockIdx.x * 128;

    const int K       = (MODE == 2) ? HID_PAD : DIM;  // A pads are zeroed
    const int NB      = (MODE == 2) ? DIM : HID;      // B row count
    const int bstride = (MODE == 2) ? HID : DIM;      // B row stride
    const float* W = Wbase + (size_t)e * (size_t)NB * (size_t)bstride;

    __shared__ float As[8][128];
    __shared__ float Bs[8][128];

    const int tid  = threadIdx.x;
    const int arow = tid >> 1;           // 0..127
    const int ak   = (tid & 1) * 4;      // 0 or 4

    const bool a_valid = (m0 + arow) < cnt;
    const float* Arow = nullptr;
    if (a_valid) {
        if (MODE == 2)
            Arow = g_H + (size_t)(e * MAXM + m0 + arow) * HID_PAD;
        else
            Arow = Xg + (size_t)g_tok[e * MAXM + m0 + arow] * DIM;
    }
    const bool b_valid = (n0 + arow) < NB;
    const float* Brow = b_valid ? (W + (size_t)(n0 + arow) * bstride) : nullptr;

    const int tx = tid & 15;             // column group
    const int ty = tid >> 4;             // row group

    float acc[8][8];
#pragma unroll
    for (int i = 0; i < 8; i++)
#pragma unroll
        for (int j = 0; j < 8; j++) acc[i][j] = 0.f;

    for (int k0 = 0; k0 < K; k0 += 8) {
        float4 av = make_float4(0.f, 0.f, 0.f, 0.f);
        float4 bv = make_float4(0.f, 0.f, 0.f, 0.f);
        if (a_valid) av = *(const float4*)(Arow + k0 + ak);
        if (b_valid && (MODE != 2 || (k0 + ak) < HID))
            bv = *(const float4*)(Brow + k0 + ak);
        __syncthreads();
        As[ak + 0][arow] = av.x; As[ak + 1][arow] = av.y;
        As[ak + 2][arow] = av.z; As[ak + 3][arow] = av.w;
        Bs[ak + 0][arow] = bv.x; Bs[ak + 1][arow] = bv.y;
        Bs[ak + 2][arow] = bv.z; Bs[ak + 3][arow] = bv.w;
        __syncthreads();
#pragma unroll
        for (int kk = 0; kk < 8; kk++) {
            float a_frag[8], b_frag[8];
            *(float4*)(a_frag)     = *(const float4*)&As[kk][ty * 8];
            *(float4*)(a_frag + 4) = *(const float4*)&As[kk][ty * 8 + 4];
            *(float4*)(b_frag)     = *(const float4*)&Bs[kk][tx * 8];
            *(float4*)(b_frag + 4) = *(const float4*)&Bs[kk][tx * 8 + 4];
#pragma unroll
            for (int i = 0; i < 8; i++)
#pragma unroll
                for (int j = 0; j < 8; j++)
                    acc[i][j] += a_frag[i] * b_frag[j];
        }
    }

    // Epilogue
#pragma unroll
    for (int i = 0; i < 8; i++) {
        int row = m0 + ty * 8 + i;
        if (row >= cnt) continue;
        if (MODE == 0) {
            size_t base = (size_t)(e * MAXM + row) * HID_PAD;
#pragma unroll
            for (int j = 0; j < 8; j++) {
                int n = n0 + tx * 8 + j;
                if (n < HID) g_H[base + n] = acc[i][j];
            }
        } else if (MODE == 1) {
            size_t base = (size_t)(e * MAXM + row) * HID_PAD;
#pragma unroll
            for (int j = 0; j < 8; j++) {
                int n = n0 + tx * 8 + j;
                if (n < HID) {
                    float h1  = g_H[base + n];
                    float sig = 1.f / (1.f + __expf(-h1));
                    g_H[base + n] = h1 * sig * acc[i][j];
                } else if (n < HID_PAD) {
                    g_H[base + n] = 0.f;   // zero pads for pass-B K loop
                }
            }
        } else {
            int slot  = e * MAXM + row;
            float wv  = g_w[slot];
            int token = g_tok[slot];
            size_t base = (size_t)token * DIM + n0 + tx * 8;
#pragma unroll
            for (int j = 0; j < 8; j++)
                atomicAdd(&out[base + j], wv * acc[i][j]);
        }
    }
}

// ---------------------------------------------------------------------------
extern "C" void kernel_launch(void* const* d_in, const int* in_sizes, int n_in,
                              void* d_out, int out_size) {
    const float* x  = (const float*)d_in[0];
    const float* Wg = (const float*)d_in[1];
    const float* W1 = (const float*)d_in[2];
    const float* W2 = (const float*)d_in[3];
    const float* W3 = (const float*)d_in[4];
    float* out = (float*)d_out;

    zero_kernel<<<(NTOK * DIM + 1023) / 1024, 1024>>>(out);
    gate_kernel<<<(NTOK * 32 + 255) / 256, 256>>>(x, Wg);

    dim3 gA((HID + 127) / 128, MAXM / 128, NEXP);   // 22 x 32 x 8
    gemm_kernel<0><<<gA, 256>>>(x, W1, nullptr);
    gemm_kernel<1><<<gA, 256>>>(x, W3, nullptr);

    dim3 gB(DIM / 128, MAXM / 128, NEXP);           // 8 x 32 x 8
    gemm_kernel<2><<<gB, 256>>>(nullptr, W2, out);
}

// round 6
// speedup vs baseline: 2.9713x; 2.9713x over previous
#include <cuda_runtime.h>
#include <cstdint>
#include <math.h>

#define NTOK 4096
#define DIM 1024
#define HID 2732
#define HID_PAD 2752
#define NEXP 8
#define MAXM 4096
#define KC 32
#define NS 3
#define NCH13 (DIM / KC)       // 32
#define NCH2  (HID_PAD / KC)   // 86
#define ST13 49152             // A(16K)+B1(16K)+B3(16K)
#define ST2  32768             // A(16K)+B(16K)

__device__ float g_H  [(size_t)NEXP * MAXM * HID_PAD];
__device__ int   g_cnt[NEXP];
__device__ int   g_tok[NEXP * MAXM];
__device__ float g_w  [NEXP * MAXM];

// ---------------- helpers ----------------
__device__ __forceinline__ uint32_t smem_u32(const void* p) {
    uint32_t a;
    asm("{ .reg .u64 t; cvta.to.shared.u64 t, %1; cvt.u32.u64 %0, t; }" : "=r"(a) : "l"(p));
    return a;
}
__device__ __forceinline__ uint32_t swz(uint32_t o) { return o ^ ((o >> 3) & 0x70); }
__device__ __forceinline__ void cpa16(uint32_t dst, const void* src, bool pred) {
    int sz = pred ? 16 : 0;
    asm volatile("cp.async.cg.shared.global [%0], [%1], 16, %2;" :: "r"(dst), "l"(src), "r"(sz) : "memory");
}
#define CP_COMMIT() asm volatile("cp.async.commit_group;" ::: "memory")
#define CP_WAIT(n)  asm volatile("cp.async.wait_group %0;" :: "n"(n) : "memory")

__device__ __forceinline__ void ldsm4(uint32_t* r, uint32_t addr) {
    asm volatile("ldmatrix.sync.aligned.m8n8.x4.shared.b16 {%0,%1,%2,%3}, [%4];"
                 : "=r"(r[0]), "=r"(r[1]), "=r"(r[2]), "=r"(r[3]) : "r"(addr));
}
__device__ __forceinline__ void cvt4(uint32_t* r) {
#pragma unroll
    for (int q = 0; q < 4; q++) {
        float f = __uint_as_float(r[q]);
        asm("cvt.rna.tf32.f32 %0, %1;" : "=r"(r[q]) : "f"(f));
    }
}
__device__ __forceinline__ void mma8(float* c, const uint32_t* a, const uint32_t* b) {
    asm volatile("mma.sync.aligned.m16n8k8.row.col.f32.tf32.tf32.f32 "
                 "{%0,%1,%2,%3},{%4,%5,%6,%7},{%8,%9},{%0,%1,%2,%3};"
                 : "+f"(c[0]), "+f"(c[1]), "+f"(c[2]), "+f"(c[3])
                 : "r"(a[0]), "r"(a[1]), "r"(a[2]), "r"(a[3]), "r"(b[0]), "r"(b[1]));
}
__device__ __forceinline__ float to_tf32(float x) {
    uint32_t o; asm("cvt.rna.tf32.f32 %0, %1;" : "=r"(o) : "f"(x));
    return __uint_as_float(o);
}

// ---------------------------------------------------------------------------
__global__ void zero_kernel(float* __restrict__ out) {
    int i = blockIdx.x * blockDim.x + threadIdx.x;
    if (i < NTOK * DIM) out[i] = 0.f;
    if (i < NEXP) g_cnt[i] = 0;
}

__global__ void gate_kernel(const float* __restrict__ x, const float* __restrict__ Wg) {
    int gtid = blockIdx.x * blockDim.x + threadIdx.x;
    int tok = gtid >> 5, lane = gtid & 31;
    if (tok >= NTOK) return;
    const float* xr = x + (size_t)tok * DIM;
    float s[NEXP];
#pragma unroll
    for (int e = 0; e < NEXP; e++) s[e] = 0.f;
    for (int k = lane; k < DIM; k += 32) {
        float xv = xr[k];
#pragma unroll
        for (int e = 0; e < NEXP; e++) s[e] += xv * Wg[e * DIM + k];
    }
#pragma unroll
    for (int e = 0; e < NEXP; e++)
#pragma unroll
        for (int off = 16; off; off >>= 1) s[e] += __shfl_xor_sync(0xffffffffu, s[e], off);
    if (lane == 0) {
        int e0 = 0;
#pragma unroll
        for (int e = 1; e < NEXP; e++) if (s[e] > s[e0]) e0 = e;
        int e1 = (e0 == 0) ? 1 : 0;
#pragma unroll
        for (int e = 0; e < NEXP; e++) if (e != e0 && s[e] > s[e1]) e1 = e;
        float p1 = __expf(s[e1] - s[e0]);
        float w0 = 1.f / (1.f + p1), w1 = p1 * w0;
        int q0 = atomicAdd(&g_cnt[e0], 1);
        g_tok[e0 * MAXM + q0] = tok; g_w[e0 * MAXM + q0] = w0;
        int q1 = atomicAdd(&g_cnt[e1], 1);
        g_tok[e1 * MAXM + q1] = tok; g_w[e1 * MAXM + q1] = w1;
    }
}

// ---------------------------------------------------------------------------
// MODE 0: D1 = Xg@W1^T, D3 = Xg@W3^T (tf32 mma.sync), H = tf32(silu(D1)*D3)
// MODE 1: D = H@W2^T, out[token] += w*D (atomicAdd)
template <int MODE>
__global__ void __launch_bounds__(256, 1)
moe_gemm(const float* __restrict__ A, const float* __restrict__ B1,
         const float* __restrict__ B3, float* __restrict__ out) {
    const int e   = blockIdx.z;
    const int cnt = g_cnt[e];
    const int m0  = blockIdx.y * 128;
    if (m0 >= cnt) return;
    const int n0  = blockIdx.x * 128;
    const int tid = threadIdx.x;
    const int wid = tid >> 5, lane = tid & 31;
    const int wm = wid >> 2, wn = wid & 3;      // warp tile: 64M x 32N
    const int NCH = (MODE == 0) ? NCH13 : NCH2;
    const int STG = (MODE == 0) ? ST13 : ST2;

    extern __shared__ char dynsm[];
    uint32_t tiles = (smem_u32(dynsm) + 1023) & ~1023u;

    // ---- fill mapping: row = tid>>1, 4 x 16B groups starting (tid&1)*4 ----
    const int frow = tid >> 1;
    const int fg0  = (tid & 1) * 4;
    uint32_t off[4];
#pragma unroll
    for (int g = 0; g < 4; g++) off[g] = swz(frow * 128 + (fg0 + g) * 16);

    const bool aok = (m0 + frow) < cnt;
    const float* aptr;
    if (MODE == 0)
        aptr = A + (size_t)(aok ? g_tok[e * MAXM + m0 + frow] : 0) * DIM;
    else
        aptr = g_H + (size_t)(e * MAXM + m0 + frow) * HID_PAD;
    const bool bok = (MODE == 0) ? ((n0 + frow) < HID) : true;
    const int brow = bok ? (n0 + frow) : 0;
    const float* b1ptr;
    const float* b3ptr = nullptr;
    if (MODE == 0) {
        b1ptr = B1 + ((size_t)e * HID + brow) * DIM;
        b3ptr = B3 + ((size_t)e * HID + brow) * DIM;
    } else {
        b1ptr = B1 + ((size_t)e * DIM + brow) * HID;
    }

    auto fill = [&](int c) {
        int k0 = c * KC;
        uint32_t sb = tiles + (c % NS) * STG;
#pragma unroll
        for (int g = 0; g < 4; g++) {
            int kf = k0 + (fg0 + g) * 4;
            cpa16(sb + off[g], aptr + kf, aok);
            bool bp = bok && (MODE == 0 || kf < HID);
            cpa16(sb + 16384 + off[g], b1ptr + kf, bp);
            if (MODE == 0) cpa16(sb + 32768 + off[g], b3ptr + kf, bp);
        }
        CP_COMMIT();
    };

    // ---- ldmatrix address bases ----
    const int sub = lane >> 3, r8 = lane & 7;
    const uint32_t a_rowoff = (uint32_t)(wm * 64 + (sub & 1) * 8 + r8) * 128 + (sub >> 1) * 16;
    const uint32_t b_rowoff = (uint32_t)(wn * 32 + (sub >> 1) * 8 + r8) * 128 + (sub & 1) * 16;

    float acc1[4][4][4];
    float acc3[MODE == 0 ? 4 : 1][4][4];
#pragma unroll
    for (int i = 0; i < 4; i++)
#pragma unroll
        for (int j = 0; j < 4; j++)
#pragma unroll
            for (int q = 0; q < 4; q++) {
                acc1[i][j][q] = 0.f;
                if (MODE == 0) acc3[i][j][q] = 0.f;
            }

#pragma unroll
    for (int i = 0; i < NS - 1; i++) fill(i);

    for (int c = 0; c < NCH; c++) {
        if (c + NS - 1 < NCH) { fill(c + NS - 1); CP_WAIT(NS - 1); }
        else                  { CP_WAIT(0); }
        __syncthreads();
        uint32_t sb = tiles + (c % NS) * STG;
        uint32_t As = sb, Bs1 = sb + 16384, Bs3 = sb + 32768;
#pragma unroll
        for (int ks = 0; ks < 4; ks++) {
            uint32_t af[4][4];
#pragma unroll
            for (int i = 0; i < 4; i++) {
                ldsm4(af[i], As + swz(a_rowoff + i * 2048 + ks * 32));
                cvt4(af[i]);
            }
            uint32_t bf1[2][4], bf3[2][4];
#pragma unroll
            for (int jj = 0; jj < 2; jj++) {
                ldsm4(bf1[jj], Bs1 + swz(b_rowoff + jj * 2048 + ks * 32));
                cvt4(bf1[jj]);
                if (MODE == 0) {
                    ldsm4(bf3[jj], Bs3 + swz(b_rowoff + jj * 2048 + ks * 32));
                    cvt4(bf3[jj]);
                }
            }
#pragma unroll
            for (int i = 0; i < 4; i++)
#pragma unroll
                for (int j = 0; j < 4; j++) {
                    mma8(acc1[i][j], af[i], &bf1[j >> 1][(j & 1) * 2]);
                    if (MODE == 0)
                        mma8(acc3[i][j], af[i], &bf3[j >> 1][(j & 1) * 2]);
                }
        }
        __syncthreads();
    }

    // ---- epilogue ----
#pragma unroll
    for (int i = 0; i < 4; i++) {
        int r0 = m0 + wm * 64 + i * 16 + (lane >> 2);
#pragma unroll
        for (int j = 0; j < 4; j++) {
            int col = n0 + wn * 32 + j * 8 + (lane & 3) * 2;
            if (MODE == 0) {
#pragma unroll
                for (int p = 0; p < 2; p++) {
                    int row = r0 + p * 8;
                    if (row >= cnt) continue;
                    float* dst = g_H + (size_t)(e * MAXM + row) * HID_PAD + col;
                    if (col < HID) {
                        float d1a = acc1[i][j][2 * p],     d3a = acc3[i][j][2 * p];
                        float d1b = acc1[i][j][2 * p + 1], d3b = acc3[i][j][2 * p + 1];
                        float ha = to_tf32(d1a * (1.f / (1.f + __expf(-d1a))) * d3a);
                        float hb = to_tf32(d1b * (1.f / (1.f + __expf(-d1b))) * d3b);
                        *(float2*)dst = make_float2(ha, hb);
                    } else if (col < HID_PAD) {
                        *(float2*)dst = make_float2(0.f, 0.f);
                    }
                }
            } else {
#pragma unroll
                for (int p = 0; p < 2; p++) {
                    int row = r0 + p * 8;
                    if (row >= cnt) continue;
                    int slot = e * MAXM + row;
                    float wv = g_w[slot];
                    float* o = out + (size_t)g_tok[slot] * DIM + col;
                    atomicAdd(o,     wv * acc1[i][j][2 * p]);
                    atomicAdd(o + 1, wv * acc1[i][j][2 * p + 1]);
                }
            }
        }
    }
}

// ---------------------------------------------------------------------------
extern "C" void kernel_launch(void* const* d_in, const int* in_sizes, int n_in,
                              void* d_out, int out_size) {
    const float* x  = (const float*)d_in[0];
    const float* Wg = (const float*)d_in[1];
    const float* W1 = (const float*)d_in[2];
    const float* W2 = (const float*)d_in[3];
    const float* W3 = (const float*)d_in[4];
    float* out = (float*)d_out;

    static int attr_set = 0;
    if (!attr_set) {
        cudaFuncSetAttribute(moe_gemm<0>, cudaFuncAttributeMaxDynamicSharedMemorySize, NS * ST13);
        cudaFuncSetAttribute(moe_gemm<1>, cudaFuncAttributeMaxDynamicSharedMemorySize, NS * ST2);
        attr_set = 1;
    }

    zero_kernel<<<(NTOK * DIM + 1023) / 1024, 1024>>>(out);
    gate_kernel<<<(NTOK * 32 + 255) / 256, 256>>>(x, Wg);

    dim3 g13((HID + 127) / 128, MAXM / 128, NEXP);   // 22 x 32 x 8
    moe_gemm<0><<<g13, 256, NS * ST13>>>(x, W1, W3, nullptr);

    dim3 g2(DIM / 128, MAXM / 128, NEXP);            // 8 x 32 x 8
    moe_gemm<1><<<g2, 256, NS * ST2>>>(nullptr, W2, nullptr, out);
}

// round 8
// speedup vs baseline: 3.6072x; 1.2140x over previous
#include <cuda_runtime.h>
#include <cstdint>
#include <math.h>

#define NTOK 4096
#define DIM 1024
#define HID 2732
#define HID_PAD 2752
#define NEXP 8
#define MAXM 4096
#define KC 32
#define NCH13 (DIM / KC)       // 32
#define NCH2  (HID_PAD / KC)   // 86
#define ST13 49152             // A(16K)+B1(16K)+B3(16K)
#define ST2  32768             // A(16K)+B(16K)

__device__ float g_H  [(size_t)NEXP * MAXM * HID_PAD];
__device__ int   g_cnt[NEXP];
__device__ int   g_tok[NEXP * MAXM];
__device__ float g_w  [NEXP * MAXM];

// ---------------- helpers ----------------
__device__ __forceinline__ uint32_t smem_u32(const void* p) {
    uint32_t a;
    asm("{ .reg .u64 t; cvta.to.shared.u64 t, %1; cvt.u32.u64 %0, t; }" : "=r"(a) : "l"(p));
    return a;
}
__device__ __forceinline__ uint32_t swz(uint32_t o) { return o ^ ((o >> 3) & 0x70); }
__device__ __forceinline__ void cpa16(uint32_t dst, const void* src, bool pred) {
    int sz = pred ? 16 : 0;
    asm volatile("cp.async.cg.shared.global [%0], [%1], 16, %2;" :: "r"(dst), "l"(src), "r"(sz) : "memory");
}
#define CP_COMMIT() asm volatile("cp.async.commit_group;" ::: "memory")
#define CP_WAIT(n)  asm volatile("cp.async.wait_group %0;" :: "n"(n) : "memory")

__device__ __forceinline__ void ldsm4(uint32_t* r, uint32_t addr) {
    asm volatile("ldmatrix.sync.aligned.m8n8.x4.shared.b16 {%0,%1,%2,%3}, [%4];"
                 : "=r"(r[0]), "=r"(r[1]), "=r"(r[2]), "=r"(r[3]) : "r"(addr));
}
__device__ __forceinline__ void cvt4(uint32_t* r) {
#pragma unroll
    for (int q = 0; q < 4; q++) {
        float f = __uint_as_float(r[q]);
        asm("cvt.rna.tf32.f32 %0, %1;" : "=r"(r[q]) : "f"(f));
    }
}
__device__ __forceinline__ void mma8(float* c, const uint32_t* a, const uint32_t* b) {
    asm volatile("mma.sync.aligned.m16n8k8.row.col.f32.tf32.tf32.f32 "
                 "{%0,%1,%2,%3},{%4,%5,%6,%7},{%8,%9},{%0,%1,%2,%3};"
                 : "+f"(c[0]), "+f"(c[1]), "+f"(c[2]), "+f"(c[3])
                 : "r"(a[0]), "r"(a[1]), "r"(a[2]), "r"(a[3]), "r"(b[0]), "r"(b[1]));
}
__device__ __forceinline__ float to_tf32(float x) {
    uint32_t o; asm("cvt.rna.tf32.f32 %0, %1;" : "=r"(o) : "f"(x));
    return __uint_as_float(o);
}

// ---------------------------------------------------------------------------
__global__ void zero_kernel(float* __restrict__ out) {
    int i = blockIdx.x * blockDim.x + threadIdx.x;
    if (i < NTOK * DIM) out[i] = 0.f;
    if (i < NEXP) g_cnt[i] = 0;
}

__global__ void gate_kernel(const float* __restrict__ x, const float* __restrict__ Wg) {
    int gtid = blockIdx.x * blockDim.x + threadIdx.x;
    int tok = gtid >> 5, lane = gtid & 31;
    if (tok >= NTOK) return;
    const float* xr = x + (size_t)tok * DIM;
    float s[NEXP];
#pragma unroll
    for (int e = 0; e < NEXP; e++) s[e] = 0.f;
    for (int k = lane; k < DIM; k += 32) {
        float xv = xr[k];
#pragma unroll
        for (int e = 0; e < NEXP; e++) s[e] += xv * Wg[e * DIM + k];
    }
#pragma unroll
    for (int e = 0; e < NEXP; e++)
#pragma unroll
        for (int off = 16; off; off >>= 1) s[e] += __shfl_xor_sync(0xffffffffu, s[e], off);
    if (lane == 0) {
        int e0 = 0;
#pragma unroll
        for (int e = 1; e < NEXP; e++) if (s[e] > s[e0]) e0 = e;
        int e1 = (e0 == 0) ? 1 : 0;
#pragma unroll
        for (int e = 0; e < NEXP; e++) if (e != e0 && s[e] > s[e1]) e1 = e;
        float p1 = __expf(s[e1] - s[e0]);
        float w0 = 1.f / (1.f + p1), w1 = p1 * w0;
        int q0 = atomicAdd(&g_cnt[e0], 1);
        g_tok[e0 * MAXM + q0] = tok; g_w[e0 * MAXM + q0] = w0;
        int q1 = atomicAdd(&g_cnt[e1], 1);
        g_tok[e1 * MAXM + q1] = tok; g_w[e1 * MAXM + q1] = w1;
    }
}

// ---------------------------------------------------------------------------
// 512 threads, 16 warps in 4x4 grid, warp tile 32x32, CTA tile 128x128.
// MODE 0: D1 = Xg@W1^T, D3 = Xg@W3^T, H = tf32(silu(D1)*D3)   (NS=3)
// MODE 1: D = H@W2^T, out[token] += w*D (atomicAdd)            (NS=4)
template <int MODE>
__global__ void __launch_bounds__(512, 1)
moe_gemm(const float* __restrict__ A, const float* __restrict__ B1,
         const float* __restrict__ B3, float* __restrict__ out) {
    constexpr int NSx = (MODE == 0) ? 3 : 4;
    constexpr int NCH = (MODE == 0) ? NCH13 : NCH2;
    constexpr int STG = (MODE == 0) ? ST13 : ST2;
    constexpr int NI  = (MODE == 0) ? 2 : 2;   // A sub-tiles (m16) per warp

    const int e   = blockIdx.z;
    const int cnt = g_cnt[e];
    const int m0  = blockIdx.y * 128;
    if (m0 >= cnt) return;
    const int n0  = blockIdx.x * 128;
    const int tid = threadIdx.x;
    const int wid = tid >> 5, lane = tid & 31;
    const int wm = wid >> 2, wn = wid & 3;      // 4x4 warps, tile 32M x 32N

    extern __shared__ char dynsm[];
    uint32_t tiles = (smem_u32(dynsm) + 1023) & ~1023u;

    // ---- fill mapping: 512 thr; row = tid>>2; 16B groups (tid&3) and (tid&3)+4
    const int frow = tid >> 2;
    const int fg   = tid & 3;
    uint32_t off[2];
#pragma unroll
    for (int g = 0; g < 2; g++) off[g] = swz(frow * 128 + (fg + 4 * g) * 16);

    const bool aok = (m0 + frow) < cnt;
    const float* aptr;
    if (MODE == 0)
        aptr = A + (size_t)(aok ? g_tok[e * MAXM + m0 + frow] : 0) * DIM;
    else
        aptr = g_H + (size_t)(e * MAXM + m0 + frow) * HID_PAD;
    const bool bok = (MODE == 0) ? ((n0 + frow) < HID) : true;
    const int brow = bok ? (n0 + frow) : 0;
    const float* b1ptr;
    const float* b3ptr = nullptr;
    if (MODE == 0) {
        b1ptr = B1 + ((size_t)e * HID + brow) * DIM;
        b3ptr = B3 + ((size_t)e * HID + brow) * DIM;
    } else {
        b1ptr = B1 + ((size_t)e * DIM + brow) * HID;
    }

    auto fill = [&](int c) {
        int k0 = c * KC;
        uint32_t sb = tiles + (c % NSx) * STG;
#pragma unroll
        for (int g = 0; g < 2; g++) {
            int kf = k0 + (fg + 4 * g) * 4;
            cpa16(sb + off[g], aptr + kf, aok);
            bool bp = bok && (MODE == 0 || kf < HID);
            cpa16(sb + 16384 + off[g], b1ptr + kf, bp);
            if (MODE == 0) cpa16(sb + 32768 + off[g], b3ptr + kf, bp);
        }
        CP_COMMIT();
    };

    // ---- ldmatrix bases (warp tile 32x32) ----
    const int sub = lane >> 3, r8 = lane & 7;
    const uint32_t a_rowoff = (uint32_t)(wm * 32 + (sub & 1) * 8 + r8) * 128 + (sub >> 1) * 16;
    const uint32_t b_rowoff = (uint32_t)(wn * 32 + (sub >> 1) * 8 + r8) * 128 + (sub & 1) * 16;

    float acc1[NI][4][4];
    float acc3[MODE == 0 ? NI : 1][4][4];
#pragma unroll
    for (int i = 0; i < NI; i++)
#pragma unroll
        for (int j = 0; j < 4; j++)
#pragma unroll
            for (int q = 0; q < 4; q++) {
                acc1[i][j][q] = 0.f;
                if (MODE == 0) acc3[i][j][q] = 0.f;
            }

#pragma unroll
    for (int i = 0; i < NSx - 1; i++) fill(i);

    for (int c = 0; c < NCH; c++) {
        // chunk c complete when at most min(NSx-2, NCH-1-c) newer groups pending
        int rem = NCH - 1 - c;
        if (NSx == 3) {
            if (rem >= 1) { CP_WAIT(1); } else { CP_WAIT(0); }
        } else {
            if (rem >= 2) { CP_WAIT(2); }
            else if (rem == 1) { CP_WAIT(1); }
            else { CP_WAIT(0); }
        }
        __syncthreads();
        if (c + NSx - 1 < NCH) fill(c + NSx - 1);   // writes stage (c-1)%NSx: safe post-sync

        uint32_t sb = tiles + (c % NSx) * STG;
        uint32_t As = sb, Bs1 = sb + 16384, Bs3 = sb + 32768;
#pragma unroll
        for (int ks = 0; ks < 4; ks++) {
            uint32_t af[NI][4];
#pragma unroll
            for (int i = 0; i < NI; i++) {
                ldsm4(af[i], As + swz(a_rowoff + i * 2048 + ks * 32));
                cvt4(af[i]);
            }
            uint32_t bf1[2][4], bf3[2][4];
#pragma unroll
            for (int jj = 0; jj < 2; jj++) {
                ldsm4(bf1[jj], Bs1 + swz(b_rowoff + jj * 2048 + ks * 32));
                cvt4(bf1[jj]);
                if (MODE == 0) {
                    ldsm4(bf3[jj], Bs3 + swz(b_rowoff + jj * 2048 + ks * 32));
                    cvt4(bf3[jj]);
                }
            }
#pragma unroll
            for (int i = 0; i < NI; i++)
#pragma unroll
                for (int j = 0; j < 4; j++) {
                    mma8(acc1[i][j], af[i], &bf1[j >> 1][(j & 1) * 2]);
                    if (MODE == 0)
                        mma8(acc3[i][j], af[i], &bf3[j >> 1][(j & 1) * 2]);
                }
        }
    }

    // ---- epilogue ----
#pragma unroll
    for (int i = 0; i < NI; i++) {
        int r0 = m0 + wm * 32 + i * 16 + (lane >> 2);
#pragma unroll
        for (int j = 0; j < 4; j++) {
            int col = n0 + wn * 32 + j * 8 + (lane & 3) * 2;
            if (MODE == 0) {
#pragma unroll
                for (int p = 0; p < 2; p++) {
                    int row = r0 + p * 8;
                    if (row >= cnt) continue;
                    float* dst = g_H + (size_t)(e * MAXM + row) * HID_PAD + col;
                    if (col < HID) {
                        float d1a = acc1[i][j][2 * p],     d3a = acc3[i][j][2 * p];
                        float d1b = acc1[i][j][2 * p + 1], d3b = acc3[i][j][2 * p + 1];
                        float ha = to_tf32(d1a * (1.f / (1.f + __expf(-d1a))) * d3a);
                        float hb = to_tf32(d1b * (1.f / (1.f + __expf(-d1b))) * d3b);
                        *(float2*)dst = make_float2(ha, hb);
                    } else if (col < HID_PAD) {
                        *(float2*)dst = make_float2(0.f, 0.f);
                    }
                }
            } else {
#pragma unroll
                for (int p = 0; p < 2; p++) {
                    int row = r0 + p * 8;
                    if (row >= cnt) continue;
                    int slot = e * MAXM + row;
                    float wv = g_w[slot];
                    float* o = out + (size_t)g_tok[slot] * DIM + col;
                    atomicAdd(o,     wv * acc1[i][j][2 * p]);
                    atomicAdd(o + 1, wv * acc1[i][j][2 * p + 1]);
                }
            }
        }
    }
}

// ---------------------------------------------------------------------------
extern "C" void kernel_launch(void* const* d_in, const int* in_sizes, int n_in,
                              void* d_out, int out_size) {
    const float* x  = (const float*)d_in[0];
    const float* Wg = (const float*)d_in[1];
    const float* W1 = (const float*)d_in[2];
    const float* W2 = (const float*)d_in[3];
    const float* W3 = (const float*)d_in[4];
    float* out = (float*)d_out;

    static int attr_set = 0;
    if (!attr_set) {
        cudaFuncSetAttribute(moe_gemm<0>, cudaFuncAttributeMaxDynamicSharedMemorySize, 3 * ST13);
        cudaFuncSetAttribute(moe_gemm<1>, cudaFuncAttributeMaxDynamicSharedMemorySize, 4 * ST2);
        attr_set = 1;
    }

    zero_kernel<<<(NTOK * DIM + 1023) / 1024, 1024>>>(out);
    gate_kernel<<<(NTOK * 32 + 255) / 256, 256>>>(x, Wg);

    dim3 g13((HID + 127) / 128, MAXM / 128, NEXP);   // 22 x 32 x 8
    moe_gemm<0><<<g13, 512, 3 * ST13>>>(x, W1, W3, nullptr);

    dim3 g2(DIM / 128, MAXM / 128, NEXP);            // 8 x 32 x 8
    moe_gemm<1><<<g2, 512, 4 * ST2>>>(nullptr, W2, nullptr, out);
}

// round 10
// speedup vs baseline: 3.6792x; 1.0200x over previous
#include <cuda_runtime.h>
#include <cstdint>
#include <math.h>

#define NTOK 4096
#define DIM 1024
#define HID 2732
#define HID_PAD 2752
#define NEXP 8
#define MAXM 4096
#define KC 32
#define NCH13 (DIM / KC)       // 32
#define NCH2  (HID_PAD / KC)   // 86
#define ST13 49152             // A(16K)+B1(16K)+B3(16K)
#define ST2  32768             // A(16K)+B(16K)

__device__ float g_xr [(size_t)NTOK * DIM];
__device__ float g_W1r[(size_t)NEXP * HID * DIM];
__device__ float g_W3r[(size_t)NEXP * HID * DIM];
__device__ float g_W2r[(size_t)NEXP * DIM * HID];
__device__ float g_H  [(size_t)NEXP * MAXM * HID_PAD];
__device__ int   g_cnt[NEXP];
__device__ int   g_tok[NEXP * MAXM];
__device__ float g_w  [NEXP * MAXM];

// ---------------- helpers ----------------
__device__ __forceinline__ uint32_t smem_u32(const void* p) {
    uint32_t a;
    asm("{ .reg .u64 t; cvta.to.shared.u64 t, %1; cvt.u32.u64 %0, t; }" : "=r"(a) : "l"(p));
    return a;
}
__device__ __forceinline__ uint32_t swz(uint32_t o) { return o ^ ((o >> 3) & 0x70); }
__device__ __forceinline__ void cpa16(uint32_t dst, const void* src, bool pred) {
    int sz = pred ? 16 : 0;
    asm volatile("cp.async.cg.shared.global [%0], [%1], 16, %2;" :: "r"(dst), "l"(src), "r"(sz) : "memory");
}
#define CP_COMMIT() asm volatile("cp.async.commit_group;" ::: "memory")
#define CP_WAIT(n)  asm volatile("cp.async.wait_group %0;" :: "n"(n) : "memory")

__device__ __forceinline__ void ldsm4(uint32_t* r, uint32_t addr) {
    asm volatile("ldmatrix.sync.aligned.m8n8.x4.shared.b16 {%0,%1,%2,%3}, [%4];"
                 : "=r"(r[0]), "=r"(r[1]), "=r"(r[2]), "=r"(r[3]) : "r"(addr));
}
__device__ __forceinline__ void mma8(float* c, const uint32_t* a, const uint32_t* b) {
    asm volatile("mma.sync.aligned.m16n8k8.row.col.f32.tf32.tf32.f32 "
                 "{%0,%1,%2,%3},{%4,%5,%6,%7},{%8,%9},{%0,%1,%2,%3};"
                 : "+f"(c[0]), "+f"(c[1]), "+f"(c[2]), "+f"(c[3])
                 : "r"(a[0]), "r"(a[1]), "r"(a[2]), "r"(a[3]), "r"(b[0]), "r"(b[1]));
}
__device__ __forceinline__ float to_tf32(float x) {
    uint32_t o; asm("cvt.rna.tf32.f32 %0, %1;" : "=r"(o) : "f"(x));
    return __uint_as_float(o);
}

// ---------------------------------------------------------------------------
__global__ void zero_kernel(float* __restrict__ out) {
    int i = blockIdx.x * blockDim.x + threadIdx.x;
    if (i < NTOK * DIM) out[i] = 0.f;
    if (i < NEXP) g_cnt[i] = 0;
}

__global__ void round_kernel(const float* __restrict__ src, float* __restrict__ dst, int n4) {
    for (int i = blockIdx.x * blockDim.x + threadIdx.x; i < n4; i += gridDim.x * blockDim.x) {
        float4 v = ((const float4*)src)[i];
        v.x = to_tf32(v.x); v.y = to_tf32(v.y); v.z = to_tf32(v.z); v.w = to_tf32(v.w);
        ((float4*)dst)[i] = v;
    }
}

__global__ void gate_kernel(const float* __restrict__ x, const float* __restrict__ Wg) {
    int gtid = blockIdx.x * blockDim.x + threadIdx.x;
    int tok = gtid >> 5, lane = gtid & 31;
    if (tok >= NTOK) return;
    const float* xr = x + (size_t)tok * DIM;
    float s[NEXP];
#pragma unroll
    for (int e = 0; e < NEXP; e++) s[e] = 0.f;
    for (int k = lane; k < DIM; k += 32) {
        float xv = xr[k];
#pragma unroll
        for (int e = 0; e < NEXP; e++) s[e] += xv * Wg[e * DIM + k];
    }
#pragma unroll
    for (int e = 0; e < NEXP; e++)
#pragma unroll
        for (int off = 16; off; off >>= 1) s[e] += __shfl_xor_sync(0xffffffffu, s[e], off);
    if (lane == 0) {
        int e0 = 0;
#pragma unroll
        for (int e = 1; e < NEXP; e++) if (s[e] > s[e0]) e0 = e;
        int e1 = (e0 == 0) ? 1 : 0;
#pragma unroll
        for (int e = 0; e < NEXP; e++) if (e != e0 && s[e] > s[e1]) e1 = e;
        float p1 = __expf(s[e1] - s[e0]);
        float w0 = 1.f / (1.f + p1), w1 = p1 * w0;
        int q0 = atomicAdd(&g_cnt[e0], 1);
        g_tok[e0 * MAXM + q0] = tok; g_w[e0 * MAXM + q0] = w0;
        int q1 = atomicAdd(&g_cnt[e1], 1);
        g_tok[e1 * MAXM + q1] = tok; g_w[e1 * MAXM + q1] = w1;
    }
}

// ---------------------------------------------------------------------------
// 512 threads, 16 warps in 4x4 grid, warp tile 32x32, CTA tile 128x128.
// All operands pre-rounded to tf32 -> NO cvt in the mainloop.
// MODE 0: D1 = Xg@W1^T, D3 = Xg@W3^T, H = tf32(silu(D1)*D3)   (NS=4)
// MODE 1: D = H@W2^T, out[token] += w*D (atomicAdd)            (NS=4)
template <int MODE>
__global__ void __launch_bounds__(512, 1)
moe_gemm(float* __restrict__ out) {
    constexpr int NSx = 4;
    constexpr int NCH = (MODE == 0) ? NCH13 : NCH2;
    constexpr int STG = (MODE == 0) ? ST13 : ST2;
    constexpr int NI  = 2;

    const int e   = blockIdx.z;
    const int cnt = g_cnt[e];
    const int m0  = blockIdx.y * 128;
    if (m0 >= cnt) return;
    const int n0  = blockIdx.x * 128;
    const int tid = threadIdx.x;
    const int wid = tid >> 5, lane = tid & 31;
    const int wm = wid >> 2, wn = wid & 3;

    extern __shared__ char dynsm[];
    uint32_t tiles = (smem_u32(dynsm) + 1023) & ~1023u;

    // fill mapping: row = tid>>2; two 16B groups
    const int frow = tid >> 2;
    const int fg   = tid & 3;
    uint32_t off[2];
#pragma unroll
    for (int g = 0; g < 2; g++) off[g] = swz(frow * 128 + (fg + 4 * g) * 16);

    const bool aok = (m0 + frow) < cnt;
    const float* aptr;
    if (MODE == 0)
        aptr = g_xr + (size_t)(aok ? g_tok[e * MAXM + m0 + frow] : 0) * DIM;
    else
        aptr = g_H + (size_t)(e * MAXM + m0 + frow) * HID_PAD;
    const bool bok = (MODE == 0) ? ((n0 + frow) < HID) : true;
    const int brow = bok ? (n0 + frow) : 0;
    const float* b1ptr;
    const float* b3ptr = nullptr;
    if (MODE == 0) {
        b1ptr = g_W1r + ((size_t)e * HID + brow) * DIM;
        b3ptr = g_W3r + ((size_t)e * HID + brow) * DIM;
    } else {
        b1ptr = g_W2r + ((size_t)e * DIM + brow) * HID;
    }

    auto fill = [&](int c, int stg) {
        int k0 = c * KC;
        uint32_t sb = tiles + stg * STG;
#pragma unroll
        for (int g = 0; g < 2; g++) {
            int kf = k0 + (fg + 4 * g) * 4;
            cpa16(sb + off[g], aptr + kf, aok);
            bool bp = bok && (MODE == 0 || kf < HID);
            cpa16(sb + 16384 + off[g], b1ptr + kf, bp);
            if (MODE == 0) cpa16(sb + 32768 + off[g], b3ptr + kf, bp);
        }
        CP_COMMIT();
    };

    const int sub = lane >> 3, r8 = lane & 7;
    const uint32_t a_rowoff = (uint32_t)(wm * 32 + (sub & 1) * 8 + r8) * 128 + (sub >> 1) * 16;
    const uint32_t b_rowoff = (uint32_t)(wn * 32 + (sub >> 1) * 8 + r8) * 128 + (sub & 1) * 16;

    float acc1[NI][4][4];
    float acc3[MODE == 0 ? NI : 1][4][4];
#pragma unroll
    for (int i = 0; i < NI; i++)
#pragma unroll
        for (int j = 0; j < 4; j++)
#pragma unroll
            for (int q = 0; q < 4; q++) {
                acc1[i][j][q] = 0.f;
                if (MODE == 0) acc3[i][j][q] = 0.f;
            }

#pragma unroll
    for (int i = 0; i < NSx - 1; i++) fill(i, i);

    int stg = 0, fstg = NSx - 1;
    for (int c = 0; c < NCH; c++) {
        int rem = NCH - 1 - c;
        if (rem >= 2)      { CP_WAIT(2); }
        else if (rem == 1) { CP_WAIT(1); }
        else               { CP_WAIT(0); }
        __syncthreads();
        if (c + NSx - 1 < NCH) {
            fill(c + NSx - 1, fstg);
            if (++fstg == NSx) fstg = 0;
        }

        uint32_t sb = tiles + stg * STG;
        if (++stg == NSx) stg = 0;
        uint32_t As = sb, Bs1 = sb + 16384, Bs3 = sb + 32768;
#pragma unroll
        for (int ks = 0; ks < 4; ks++) {
            uint32_t af[NI][4];
#pragma unroll
            for (int i = 0; i < NI; i++)
                ldsm4(af[i], As + swz(a_rowoff + i * 2048 + ks * 32));
            uint32_t bf1[2][4], bf3[2][4];
#pragma unroll
            for (int jj = 0; jj < 2; jj++) {
                ldsm4(bf1[jj], Bs1 + swz(b_rowoff + jj * 2048 + ks * 32));
                if (MODE == 0)
                    ldsm4(bf3[jj], Bs3 + swz(b_rowoff + jj * 2048 + ks * 32));
            }
#pragma unroll
            for (int i = 0; i < NI; i++)
#pragma unroll
                for (int j = 0; j < 4; j++) {
                    mma8(acc1[i][j], af[i], &bf1[j >> 1][(j & 1) * 2]);
                    if (MODE == 0)
                        mma8(acc3[i][j], af[i], &bf3[j >> 1][(j & 1) * 2]);
                }
        }
    }

    // ---- epilogue ----
#pragma unroll
    for (int i = 0; i < NI; i++) {
        int r0 = m0 + wm * 32 + i * 16 + (lane >> 2);
#pragma unroll
        for (int j = 0; j < 4; j++) {
            int col = n0 + wn * 32 + j * 8 + (lane & 3) * 2;
            if (MODE == 0) {
#pragma unroll
                for (int p = 0; p < 2; p++) {
                    int row = r0 + p * 8;
                    if (row >= cnt) continue;
                    float* dst = g_H + (size_t)(e * MAXM + row) * HID_PAD + col;
                    if (col < HID) {
                        float d1a = acc1[i][j][2 * p],     d3a = acc3[i][j][2 * p];
                        float d1b = acc1[i][j][2 * p + 1], d3b = acc3[i][j][2 * p + 1];
                        float ha = to_tf32(d1a * (1.f / (1.f + __expf(-d1a))) * d3a);
                        float hb = to_tf32(d1b * (1.f / (1.f + __expf(-d1b))) * d3b);
                        *(float2*)dst = make_float2(ha, hb);
                    } else if (col < HID_PAD) {
                        *(float2*)dst = make_float2(0.f, 0.f);
                    }
                }
            } else {
#pragma unroll
                for (int p = 0; p < 2; p++) {
                    int row = r0 + p * 8;
                    if (row >= cnt) continue;
                    int slot = e * MAXM + row;
                    float wv = g_w[slot];
                    float* o = out + (size_t)g_tok[slot] * DIM + col;
                    atomicAdd(o,     wv * acc1[i][j][2 * p]);
                    atomicAdd(o + 1, wv * acc1[i][j][2 * p + 1]);
                }
            }
        }
    }
}

// ---------------------------------------------------------------------------
extern "C" void kernel_launch(void* const* d_in, const int* in_sizes, int n_in,
                              void* d_out, int out_size) {
    const float* x  = (const float*)d_in[0];
    const float* Wg = (const float*)d_in[1];
    const float* W1 = (const float*)d_in[2];
    const float* W2 = (const float*)d_in[3];
    const float* W3 = (const float*)d_in[4];
    float* out = (float*)d_out;

    static int attr_set = 0;
    if (!attr_set) {
        cudaFuncSetAttribute(moe_gemm<0>, cudaFuncAttributeMaxDynamicSharedMemorySize, 4 * ST13);
        cudaFuncSetAttribute(moe_gemm<1>, cudaFuncAttributeMaxDynamicSharedMemorySize, 4 * ST2);
        attr_set = 1;
    }

    zero_kernel<<<(NTOK * DIM + 1023) / 1024, 1024>>>(out);
    gate_kernel<<<(NTOK * 32 + 255) / 256, 256>>>(x, Wg);

    float* xr;  cudaGetSymbolAddress((void**)&xr,  g_xr);
    float* w1r; cudaGetSymbolAddress((void**)&w1r, g_W1r);
    float* w2r; cudaGetSymbolAddress((void**)&w2r, g_W2r);
    float* w3r; cudaGetSymbolAddress((void**)&w3r, g_W3r);
    round_kernel<<<1184, 256>>>(x,  xr,  NTOK * DIM / 4);
    round_kernel<<<1184, 256>>>(W1, w1r, NEXP * HID * DIM / 4);
    round_kernel<<<1184, 256>>>(W2, w2r, NEXP * DIM * HID / 4);
    round_kernel<<<1184, 256>>>(W3, w3r, NEXP * HID * DIM / 4);

    dim3 g13((HID + 127) / 128, MAXM / 128, NEXP);   // 22 x 32 x 8
    moe_gemm<0><<<g13, 512, 4 * ST13>>>(nullptr);

    dim3 g2(DIM / 128, MAXM / 128, NEXP);            // 8 x 32 x 8
    moe_gemm<1><<<g2, 512, 4 * ST2>>>(out);
}

// round 12
// speedup vs baseline: 4.4776x; 1.2170x over previous
#include <cuda_runtime.h>
#include <cuda_fp16.h>
#include <cstdint>
#include <math.h>

#define NTOK 4096
#define DIM 1024
#define HID 2732
#define HID_PAD 2752
#define NEXP 8
#define MAXM 4096
#define KC 64                  // halves per K chunk (128B row)
#define NCH13 (DIM / KC)       // 16
#define NCH2  (HID_PAD / KC)   // 43
#define ST13 49152             // A(16K)+B1(16K)+B3(16K)
#define ST2  32768             // A(16K)+B(16K)

__device__ __half g_xh [(size_t)NTOK * DIM];
__device__ __half g_W1h[(size_t)NEXP * HID * DIM];
__device__ __half g_W3h[(size_t)NEXP * HID * DIM];
__device__ __half g_W2h[(size_t)NEXP * DIM * HID_PAD];   // padded cols zero
__device__ __half g_H  [(size_t)NEXP * MAXM * HID_PAD];  // padded cols zero
__device__ int    g_cnt[NEXP];
__device__ int    g_tok[NEXP * MAXM];
__device__ float  g_w  [NEXP * MAXM];

// ---------------- helpers ----------------
__device__ __forceinline__ uint32_t smem_u32(const void* p) {
    uint32_t a;
    asm("{ .reg .u64 t; cvta.to.shared.u64 t, %1; cvt.u32.u64 %0, t; }" : "=r"(a) : "l"(p));
    return a;
}
__device__ __forceinline__ uint32_t swz(uint32_t o) { return o ^ ((o >> 3) & 0x70); }
__device__ __forceinline__ void cpa16(uint32_t dst, const void* src, bool pred) {
    int sz = pred ? 16 : 0;
    asm volatile("cp.async.cg.shared.global [%0], [%1], 16, %2;" :: "r"(dst), "l"(src), "r"(sz) : "memory");
}
#define CP_COMMIT() asm volatile("cp.async.commit_group;" ::: "memory")
#define CP_WAIT(n)  asm volatile("cp.async.wait_group %0;" :: "n"(n) : "memory")

__device__ __forceinline__ void ldsm4(uint32_t* r, uint32_t addr) {
    asm volatile("ldmatrix.sync.aligned.m8n8.x4.shared.b16 {%0,%1,%2,%3}, [%4];"
                 : "=r"(r[0]), "=r"(r[1]), "=r"(r[2]), "=r"(r[3]) : "r"(addr));
}
__device__ __forceinline__ void mma16(float* c, const uint32_t* a, const uint32_t* b) {
    asm volatile("mma.sync.aligned.m16n8k16.row.col.f32.f16.f16.f32 "
                 "{%0,%1,%2,%3},{%4,%5,%6,%7},{%8,%9},{%0,%1,%2,%3};"
                 : "+f"(c[0]), "+f"(c[1]), "+f"(c[2]), "+f"(c[3])
                 : "r"(a[0]), "r"(a[1]), "r"(a[2]), "r"(a[3]), "r"(b[0]), "r"(b[1]));
}

// ---------------------------------------------------------------------------
__global__ void zero_kernel(float* __restrict__ out) {
    int i = blockIdx.x * blockDim.x + threadIdx.x;
    if (i < NTOK * DIM) out[i] = 0.f;
    if (i < NEXP) g_cnt[i] = 0;
}

// f32 -> f16 (RN), straight copy; n4 = count/4
__global__ void conv_kernel(const float* __restrict__ src, __half* __restrict__ dst, int n4) {
    for (int i = blockIdx.x * blockDim.x + threadIdx.x; i < n4; i += gridDim.x * blockDim.x) {
        float4 v = ((const float4*)src)[i];
        __half2 h0 = __floats2half2_rn(v.x, v.y);
        __half2 h1 = __floats2half2_rn(v.z, v.w);
        ((__half2*)dst)[2 * i]     = h0;
        ((__half2*)dst)[2 * i + 1] = h1;
    }
}

// W2 [E*DIM][HID] f32 -> [E*DIM][HID_PAD] f16, zero pads
__global__ void conv_pad_kernel(const float* __restrict__ src) {
    const int n2 = NEXP * DIM * (HID_PAD / 2);
    for (int i = blockIdx.x * blockDim.x + threadIdx.x; i < n2; i += gridDim.x * blockDim.x) {
        int row = i / (HID_PAD / 2);
        int h = (i % (HID_PAD / 2)) * 2;
        float a = 0.f, b = 0.f;
        if (h < HID) {                      // HID even: pair never straddles
            const float* s = src + (size_t)row * HID + h;
            a = s[0]; b = s[1];
        }
        ((__half2*)g_W2h)[i] = __floats2half2_rn(a, b);
    }
}

__global__ void gate_kernel(const float* __restrict__ x, const float* __restrict__ Wg) {
    int gtid = blockIdx.x * blockDim.x + threadIdx.x;
    int tok = gtid >> 5, lane = gtid & 31;
    if (tok >= NTOK) return;
    const float* xr = x + (size_t)tok * DIM;
    float s[NEXP];
#pragma unroll
    for (int e = 0; e < NEXP; e++) s[e] = 0.f;
    for (int k = lane; k < DIM; k += 32) {
        float xv = xr[k];
#pragma unroll
        for (int e = 0; e < NEXP; e++) s[e] += xv * Wg[e * DIM + k];
    }
#pragma unroll
    for (int e = 0; e < NEXP; e++)
#pragma unroll
        for (int off = 16; off; off >>= 1) s[e] += __shfl_xor_sync(0xffffffffu, s[e], off);
    if (lane == 0) {
        int e0 = 0;
#pragma unroll
        for (int e = 1; e < NEXP; e++) if (s[e] > s[e0]) e0 = e;
        int e1 = (e0 == 0) ? 1 : 0;
#pragma unroll
        for (int e = 0; e < NEXP; e++) if (e != e0 && s[e] > s[e1]) e1 = e;
        float p1 = __expf(s[e1] - s[e0]);
        float w0 = 1.f / (1.f + p1), w1 = p1 * w0;
        int q0 = atomicAdd(&g_cnt[e0], 1);
        g_tok[e0 * MAXM + q0] = tok; g_w[e0 * MAXM + q0] = w0;
        int q1 = atomicAdd(&g_cnt[e1], 1);
        g_tok[e1 * MAXM + q1] = tok; g_w[e1 * MAXM + q1] = w1;
    }
}

// ---------------------------------------------------------------------------
// 512 threads, 16 warps (4x4), warp tile 32x32, CTA tile 128x128, fp16 mma k16.
// MODE 0: D1 = Xg@W1^T, D3 = Xg@W3^T, H = f16(silu(D1)*D3)
// MODE 1: D = H@W2^T, out[token] += w*D (atomicAdd)
template <int MODE>
__global__ void __launch_bounds__(512, 1)
moe_gemm(float* __restrict__ out) {
    constexpr int NSx = 4;
    constexpr int NCH = (MODE == 0) ? NCH13 : NCH2;
    constexpr int STG = (MODE == 0) ? ST13 : ST2;
    constexpr int NI  = 2;

    const int e   = blockIdx.z;
    const int cnt = g_cnt[e];
    const int m0  = blockIdx.y * 128;
    if (m0 >= cnt) return;
    const int n0  = blockIdx.x * 128;
    const int tid = threadIdx.x;
    const int wid = tid >> 5, lane = tid & 31;
    const int wm = wid >> 2, wn = wid & 3;

    extern __shared__ char dynsm[];
    uint32_t tiles = (smem_u32(dynsm) + 1023) & ~1023u;

    // fill mapping: row = tid>>2; two 16B groups (8 halves each)
    const int frow = tid >> 2;
    const int fg   = tid & 3;
    uint32_t off[2];
#pragma unroll
    for (int g = 0; g < 2; g++) off[g] = swz(frow * 128 + (fg + 4 * g) * 16);

    const bool aok = (m0 + frow) < cnt;
    const __half* aptr;
    if (MODE == 0)
        aptr = g_xh + (size_t)(aok ? g_tok[e * MAXM + m0 + frow] : 0) * DIM;
    else
        aptr = g_H + (size_t)(e * MAXM + m0 + frow) * HID_PAD;
    const bool bok = (MODE == 0) ? ((n0 + frow) < HID) : true;
    const int brow = bok ? (n0 + frow) : 0;
    const __half* b1ptr;
    const __half* b3ptr = nullptr;
    if (MODE == 0) {
        b1ptr = g_W1h + ((size_t)e * HID + brow) * DIM;
        b3ptr = g_W3h + ((size_t)e * HID + brow) * DIM;
    } else {
        b1ptr = g_W2h + ((size_t)e * DIM + brow) * HID_PAD;
    }

    auto fill = [&](int c, int stg) {
        int k0 = c * KC;                      // in halves
        uint32_t sb = tiles + stg * STG;
#pragma unroll
        for (int g = 0; g < 2; g++) {
            int kf = k0 + (fg + 4 * g) * 8;   // half index of this 16B group
            cpa16(sb + off[g], aptr + kf, aok);
            cpa16(sb + 16384 + off[g], b1ptr + kf, bok);
            if (MODE == 0) cpa16(sb + 32768 + off[g], b3ptr + kf, bok);
        }
        CP_COMMIT();
    };

    // ldmatrix bases: identical lane mapping as before (fp16 x4 fragment layout)
    const int sub = lane >> 3, r8 = lane & 7;
    const uint32_t a_rowoff = (uint32_t)(wm * 32 + (sub & 1) * 8 + r8) * 128 + (sub >> 1) * 16;
    const uint32_t b_rowoff = (uint32_t)(wn * 32 + (sub >> 1) * 8 + r8) * 128 + (sub & 1) * 16;

    float acc1[NI][4][4];
    float acc3[MODE == 0 ? NI : 1][4][4];
#pragma unroll
    for (int i = 0; i < NI; i++)
#pragma unroll
        for (int j = 0; j < 4; j++)
#pragma unroll
            for (int q = 0; q < 4; q++) {
                acc1[i][j][q] = 0.f;
                if (MODE == 0) acc3[i][j][q] = 0.f;
            }

#pragma unroll
    for (int i = 0; i < NSx - 1; i++) fill(i, i);

    int stg = 0, fstg = NSx - 1;
    for (int c = 0; c < NCH; c++) {
        int rem = NCH - 1 - c;
        if (rem >= 2)      { CP_WAIT(2); }
        else if (rem == 1) { CP_WAIT(1); }
        else               { CP_WAIT(0); }
        __syncthreads();
        if (c + NSx - 1 < NCH) {
            fill(c + NSx - 1, fstg);
            if (++fstg == NSx) fstg = 0;
        }

        uint32_t sb = tiles + stg * STG;
        if (++stg == NSx) stg = 0;
        uint32_t As = sb, Bs1 = sb + 16384, Bs3 = sb + 32768;
#pragma unroll
        for (int ks = 0; ks < 4; ks++) {      // each ks = k16 (32B of the row)
            uint32_t af[NI][4];
#pragma unroll
            for (int i = 0; i < NI; i++)
                ldsm4(af[i], As + swz(a_rowoff + i * 2048 + ks * 32));
            uint32_t bf1[2][4], bf3[2][4];
#pragma unroll
            for (int jj = 0; jj < 2; jj++) {
                ldsm4(bf1[jj], Bs1 + swz(b_rowoff + jj * 2048 + ks * 32));
                if (MODE == 0)
                    ldsm4(bf3[jj], Bs3 + swz(b_rowoff + jj * 2048 + ks * 32));
            }
#pragma unroll
            for (int i = 0; i < NI; i++)
#pragma unroll
                for (int j = 0; j < 4; j++) {
                    mma16(acc1[i][j], af[i], &bf1[j >> 1][(j & 1) * 2]);
                    if (MODE == 0)
                        mma16(acc3[i][j], af[i], &bf3[j >> 1][(j & 1) * 2]);
                }
        }
    }

    // ---- epilogue ----
#pragma unroll
    for (int i = 0; i < NI; i++) {
        int r0 = m0 + wm * 32 + i * 16 + (lane >> 2);
#pragma unroll
        for (int j = 0; j < 4; j++) {
            int col = n0 + wn * 32 + j * 8 + (lane & 3) * 2;
            if (MODE == 0) {
#pragma unroll
                for (int p = 0; p < 2; p++) {
                    int row = r0 + p * 8;
                    if (row >= cnt) continue;
                    __half* dst = g_H + (size_t)(e * MAXM + row) * HID_PAD + col;
                    if (col < HID) {
                        float d1a = acc1[i][j][2 * p],     d3a = acc3[i][j][2 * p];
                        float d1b = acc1[i][j][2 * p + 1], d3b = acc3[i][j][2 * p + 1];
                        float ha = d1a * (1.f / (1.f + __expf(-d1a))) * d3a;
                        float hb = d1b * (1.f / (1.f + __expf(-d1b))) * d3b;
                        *(__half2*)dst = __floats2half2_rn(ha, hb);
                    } else if (col < HID_PAD) {
                        *(__half2*)dst = __floats2half2_rn(0.f, 0.f);
                    }
                }
            } else {
#pragma unroll
                for (int p = 0; p < 2; p++) {
                    int row = r0 + p * 8;
                    if (row >= cnt) continue;
                    int slot = e * MAXM + row;
                    float wv = g_w[slot];
                    float* o = out + (size_t)g_tok[slot] * DIM + col;
                    atomicAdd(o,     wv * acc1[i][j][2 * p]);
                    atomicAdd(o + 1, wv * acc1[i][j][2 * p + 1]);
                }
            }
        }
    }
}

// ---------------------------------------------------------------------------
extern "C" void kernel_launch(void* const* d_in, const int* in_sizes, int n_in,
                              void* d_out, int out_size) {
    const float* x  = (const float*)d_in[0];
    const float* Wg = (const float*)d_in[1];
    const float* W1 = (const float*)d_in[2];
    const float* W2 = (const float*)d_in[3];
    const float* W3 = (const float*)d_in[4];
    float* out = (float*)d_out;

    static int attr_set = 0;
    if (!attr_set) {
        cudaFuncSetAttribute(moe_gemm<0>, cudaFuncAttributeMaxDynamicSharedMemorySize, 4 * ST13 + 1024);
        cudaFuncSetAttribute(moe_gemm<1>, cudaFuncAttributeMaxDynamicSharedMemorySize, 4 * ST2 + 1024);
        attr_set = 1;
    }

    zero_kernel<<<(NTOK * DIM + 1023) / 1024, 1024>>>(out);
    gate_kernel<<<(NTOK * 32 + 255) / 256, 256>>>(x, Wg);

    __half* xh;  cudaGetSymbolAddress((void**)&xh,  g_xh);
    __half* w1h; cudaGetSymbolAddress((void**)&w1h, g_W1h);
    __half* w3h; cudaGetSymbolAddress((void**)&w3h, g_W3h);
    conv_kernel<<<1184, 256>>>(x,  xh,  NTOK * DIM / 4);
    conv_kernel<<<1184, 256>>>(W1, w1h, NEXP * HID * DIM / 4);
    conv_kernel<<<1184, 256>>>(W3, w3h, NEXP * HID * DIM / 4);
    conv_pad_kernel<<<1184, 256>>>(W2);

    dim3 g13((HID + 127) / 128, MAXM / 128, NEXP);   // 22 x 32 x 8
    moe_gemm<0><<<g13, 512, 4 * ST13 + 1024>>>(nullptr);

    dim3 g2(DIM / 128, MAXM / 128, NEXP);            // 8 x 32 x 8
    moe_gemm<1><<<g2, 512, 4 * ST2 + 1024>>>(out);
}

// round 14
// speedup vs baseline: 6.7361x; 1.5044x over previous
#include <cuda_runtime.h>
#include <cuda_fp16.h>
#include <cstdint>
#include <math.h>

#define NTOK 4096
#define DIM 1024
#define HID 2732
#define HID_PAD 2816           // 22 * 128
#define NEXP 8
#define MAXM 4096
#define KC 64                  // halves per chunk (128B row)
#define NCH13 (DIM / KC)       // 16 chunks -> 8 super
#define NCH2  (HID_PAD / KC)   // 44 chunks -> 22 super
#define NSC13 (NCH13 / 2)
#define NSC2  (NCH2 / 2)
#define ST13 49152             // per chunk: A(16K)+B1(16K)+B3(16K)
#define ST2  32768             // per chunk: A(16K)+B(16K)
#define NSS13 2                // super-stages (2 chunks each): 2*96K = 192K
#define NSS2  3                // 3*64K = 192K

__device__ __half g_xh [(size_t)NTOK * DIM];
__device__ __half g_W1h[(size_t)NEXP * HID * DIM];
__device__ __half g_W3h[(size_t)NEXP * HID * DIM];
__device__ __half g_W2h[(size_t)NEXP * DIM * HID_PAD];
__device__ __half g_H  [(size_t)NEXP * MAXM * HID_PAD];
__device__ int    g_cnt[NEXP];
__device__ int    g_tok[NEXP * MAXM];
__device__ float  g_w  [NEXP * MAXM];

// ---------------- helpers ----------------
__device__ __forceinline__ uint32_t smem_u32(const void* p) {
    uint32_t a;
    asm("{ .reg .u64 t; cvta.to.shared.u64 t, %1; cvt.u32.u64 %0, t; }" : "=r"(a) : "l"(p));
    return a;
}
__device__ __forceinline__ uint32_t swz(uint32_t o) { return o ^ ((o >> 3) & 0x70); }
__device__ __forceinline__ void cpa16(uint32_t dst, const void* src, bool pred) {
    int sz = pred ? 16 : 0;
    asm volatile("cp.async.cg.shared.global [%0], [%1], 16, %2;" :: "r"(dst), "l"(src), "r"(sz) : "memory");
}
#define CP_COMMIT() asm volatile("cp.async.commit_group;" ::: "memory")
#define CP_WAIT(n)  asm volatile("cp.async.wait_group %0;" :: "n"(n) : "memory")

__device__ __forceinline__ void ldsm4(uint32_t* r, uint32_t addr) {
    asm volatile("ldmatrix.sync.aligned.m8n8.x4.shared.b16 {%0,%1,%2,%3}, [%4];"
                 : "=r"(r[0]), "=r"(r[1]), "=r"(r[2]), "=r"(r[3]) : "r"(addr));
}
__device__ __forceinline__ void mma16(float* c, const uint32_t* a, const uint32_t* b) {
    asm volatile("mma.sync.aligned.m16n8k16.row.col.f32.f16.f16.f32 "
                 "{%0,%1,%2,%3},{%4,%5,%6,%7},{%8,%9},{%0,%1,%2,%3};"
                 : "+f"(c[0]), "+f"(c[1]), "+f"(c[2]), "+f"(c[3])
                 : "r"(a[0]), "r"(a[1]), "r"(a[2]), "r"(a[3]), "r"(b[0]), "r"(b[1]));
}

// ---------------------------------------------------------------------------
__global__ void zero_kernel(float* __restrict__ out) {
    int i = blockIdx.x * blockDim.x + threadIdx.x;
    if (i < NTOK * DIM) out[i] = 0.f;
    if (i < NEXP) g_cnt[i] = 0;
}

// f32 -> f16 (RN); n4 = count/4
__global__ void conv_kernel(const float* __restrict__ src, __half* __restrict__ dst, int n4) {
    for (int i = blockIdx.x * blockDim.x + threadIdx.x; i < n4; i += gridDim.x * blockDim.x) {
        float4 v = ((const float4*)src)[i];
        ((__half2*)dst)[2 * i]     = __floats2half2_rn(v.x, v.y);
        ((__half2*)dst)[2 * i + 1] = __floats2half2_rn(v.z, v.w);
    }
}

// W2 [E*DIM][HID] f32 -> [E*DIM][HID_PAD] f16, zero pads
__global__ void conv_pad_kernel(const float* __restrict__ src) {
    const int n2 = NEXP * DIM * (HID_PAD / 2);
    for (int i = blockIdx.x * blockDim.x + threadIdx.x; i < n2; i += gridDim.x * blockDim.x) {
        int row = i / (HID_PAD / 2);
        int h = (i % (HID_PAD / 2)) * 2;
        float a = 0.f, b = 0.f;
        if (h < HID) {
            const float* s = src + (size_t)row * HID + h;
            a = s[0]; b = s[1];
        }
        ((__half2*)g_W2h)[i] = __floats2half2_rn(a, b);
    }
}

// gate + x fp16 conversion fused
__global__ void gate_kernel(const float* __restrict__ x, const float* __restrict__ Wg) {
    int gtid = blockIdx.x * blockDim.x + threadIdx.x;
    int tok = gtid >> 5, lane = gtid & 31;
    if (tok >= NTOK) return;
    const float* xr = x + (size_t)tok * DIM;
    __half* xo = g_xh + (size_t)tok * DIM;
    float s[NEXP];
#pragma unroll
    for (int e = 0; e < NEXP; e++) s[e] = 0.f;
    for (int k = lane; k < DIM; k += 32) {
        float xv = xr[k];
        xo[k] = __float2half_rn(xv);
#pragma unroll
        for (int e = 0; e < NEXP; e++) s[e] += xv * Wg[e * DIM + k];
    }
#pragma unroll
    for (int e = 0; e < NEXP; e++)
#pragma unroll
        for (int off = 16; off; off >>= 1) s[e] += __shfl_xor_sync(0xffffffffu, s[e], off);
    if (lane == 0) {
        int e0 = 0;
#pragma unroll
        for (int e = 1; e < NEXP; e++) if (s[e] > s[e0]) e0 = e;
        int e1 = (e0 == 0) ? 1 : 0;
#pragma unroll
        for (int e = 0; e < NEXP; e++) if (e != e0 && s[e] > s[e1]) e1 = e;
        float p1 = __expf(s[e1] - s[e0]);
        float w0 = 1.f / (1.f + p1), w1 = p1 * w0;
        int q0 = atomicAdd(&g_cnt[e0], 1);
        g_tok[e0 * MAXM + q0] = tok; g_w[e0 * MAXM + q0] = w0;
        int q1 = atomicAdd(&g_cnt[e1], 1);
        g_tok[e1 * MAXM + q1] = tok; g_w[e1 * MAXM + q1] = w1;
    }
}

// ---------------------------------------------------------------------------
// 512 threads, 16 warps (4x4), warp tile 32x32, CTA tile 128x128, fp16 mma k16.
// Super-chunk = 2 K-chunks (K=128) per barrier, one commit group per super-chunk.
// Pipeline invariant (wait BEFORE barrier, fill AFTER): CP_WAIT(NSS-2).
// MODE 0: D1 = Xg@W1^T, D3 = Xg@W3^T, H = f16(silu(D1)*D3)   (NSS=2 -> wait 0)
// MODE 1: D = H@W2^T, out[token] += w*D (atomicAdd)           (NSS=3 -> wait 1)
template <int MODE>
__global__ void __launch_bounds__(512, 1)
moe_gemm(float* __restrict__ out) {
    constexpr int NSS = (MODE == 0) ? NSS13 : NSS2;
    constexpr int NSC = (MODE == 0) ? NSC13 : NSC2;
    constexpr int STG = (MODE == 0) ? ST13 : ST2;
    constexpr int SUP = 2 * STG;
    constexpr int NI  = 2;

    const int e   = blockIdx.z;
    const int cnt = g_cnt[e];
    const int m0  = blockIdx.y * 128;
    if (m0 >= cnt) return;
    const int n0  = blockIdx.x * 128;
    const int tid = threadIdx.x;
    const int wid = tid >> 5, lane = tid & 31;
    const int wm = wid >> 2, wn = wid & 3;

    extern __shared__ char dynsm[];
    uint32_t tiles = (smem_u32(dynsm) + 1023) & ~1023u;

    const int frow = tid >> 2;
    const int fg   = tid & 3;
    uint32_t off[2];
#pragma unroll
    for (int g = 0; g < 2; g++) off[g] = swz(frow * 128 + (fg + 4 * g) * 16);

    const bool aok = (m0 + frow) < cnt;
    const __half* aptr;
    if (MODE == 0)
        aptr = g_xh + (size_t)(aok ? g_tok[e * MAXM + m0 + frow] : 0) * DIM;
    else
        aptr = g_H + (size_t)(e * MAXM + m0 + frow) * HID_PAD;
    const bool bok = (MODE == 0) ? ((n0 + frow) < HID) : true;
    const int brow = bok ? (n0 + frow) : 0;
    const __half* b1ptr;
    const __half* b3ptr = nullptr;
    if (MODE == 0) {
        b1ptr = g_W1h + ((size_t)e * HID + brow) * DIM;
        b3ptr = g_W3h + ((size_t)e * HID + brow) * DIM;
    } else {
        b1ptr = g_W2h + ((size_t)e * DIM + brow) * HID_PAD;
    }

    auto fill = [&](int sc, int ss) {
        uint32_t sb0 = tiles + ss * SUP;
#pragma unroll
        for (int h = 0; h < 2; h++) {
            int k0 = (2 * sc + h) * KC;
            uint32_t sb = sb0 + h * STG;
#pragma unroll
            for (int g = 0; g < 2; g++) {
                int kf = k0 + (fg + 4 * g) * 8;
                cpa16(sb + off[g], aptr + kf, aok);
                cpa16(sb + 16384 + off[g], b1ptr + kf, bok);
                if (MODE == 0) cpa16(sb + 32768 + off[g], b3ptr + kf, bok);
            }
        }
        CP_COMMIT();
    };

    const int sub = lane >> 3, r8 = lane & 7;
    const uint32_t a_rowoff = (uint32_t)(wm * 32 + (sub & 1) * 8 + r8) * 128 + (sub >> 1) * 16;
    const uint32_t b_rowoff = (uint32_t)(wn * 32 + (sub >> 1) * 8 + r8) * 128 + (sub & 1) * 16;

    float acc1[NI][4][4];
    float acc3[MODE == 0 ? NI : 1][4][4];
#pragma unroll
    for (int i = 0; i < NI; i++)
#pragma unroll
        for (int j = 0; j < 4; j++)
#pragma unroll
            for (int q = 0; q < 4; q++) {
                acc1[i][j][q] = 0.f;
                if (MODE == 0) acc3[i][j][q] = 0.f;
            }

#pragma unroll
    for (int i = 0; i < NSS - 1; i++) fill(i, i);

    int stg = 0, fstg = NSS - 1;
    for (int sc = 0; sc < NSC; sc++) {
        // Invariant: committed groups at this point = min(sc + NSS - 1, NSC).
        // Group sc must be complete => allow at most (committed - sc - 1) newer
        // groups pending = NSS - 2 (0 at the tail).
        if (NSS == 2) {
            CP_WAIT(0);
        } else {
            if (sc + NSS - 1 <= NSC - 1) { CP_WAIT(1); } else { CP_WAIT(0); }
        }
        __syncthreads();
        if (sc + NSS - 1 < NSC) {
            fill(sc + NSS - 1, fstg);
            if (++fstg == NSS) fstg = 0;
        }

        uint32_t sb0 = tiles + stg * SUP;
        if (++stg == NSS) stg = 0;
#pragma unroll
        for (int h = 0; h < 2; h++) {
            uint32_t As = sb0 + h * STG, Bs1 = As + 16384, Bs3 = As + 32768;
#pragma unroll
            for (int ks = 0; ks < 4; ks++) {
                uint32_t af[NI][4];
#pragma unroll
                for (int i = 0; i < NI; i++)
                    ldsm4(af[i], As + swz(a_rowoff + i * 2048 + ks * 32));
                uint32_t bf1[2][4], bf3[2][4];
#pragma unroll
                for (int jj = 0; jj < 2; jj++) {
                    ldsm4(bf1[jj], Bs1 + swz(b_rowoff + jj * 2048 + ks * 32));
                    if (MODE == 0)
                        ldsm4(bf3[jj], Bs3 + swz(b_rowoff + jj * 2048 + ks * 32));
                }
#pragma unroll
                for (int i = 0; i < NI; i++)
#pragma unroll
                    for (int j = 0; j < 4; j++) {
                        mma16(acc1[i][j], af[i], &bf1[j >> 1][(j & 1) * 2]);
                        if (MODE == 0)
                            mma16(acc3[i][j], af[i], &bf3[j >> 1][(j & 1) * 2]);
                    }
            }
        }
    }

    // ---- epilogue ----
#pragma unroll
    for (int i = 0; i < NI; i++) {
        int r0 = m0 + wm * 32 + i * 16 + (lane >> 2);
#pragma unroll
        for (int j = 0; j < 4; j++) {
            int col = n0 + wn * 32 + j * 8 + (lane & 3) * 2;
            if (MODE == 0) {
#pragma unroll
                for (int p = 0; p < 2; p++) {
                    int row = r0 + p * 8;
                    if (row >= cnt) continue;
                    __half* dst = g_H + (size_t)(e * MAXM + row) * HID_PAD + col;
                    if (col < HID) {
                        float d1a = acc1[i][j][2 * p],     d3a = acc3[i][j][2 * p];
                        float d1b = acc1[i][j][2 * p + 1], d3b = acc3[i][j][2 * p + 1];
                        float ha = d1a * (1.f / (1.f + __expf(-d1a))) * d3a;
                        float hb = d1b * (1.f / (1.f + __expf(-d1b))) * d3b;
                        *(__half2*)dst = __floats2half2_rn(ha, hb);
                    } else {
                        *(__half2*)dst = __floats2half2_rn(0.f, 0.f);
                    }
                }
            } else {
#pragma unroll
                for (int p = 0; p < 2; p++) {
                    int row = r0 + p * 8;
                    if (row >= cnt) continue;
                    int slot = e * MAXM + row;
                    float wv = g_w[slot];
                    float* o = out + (size_t)g_tok[slot] * DIM + col;
                    atomicAdd(o,     wv * acc1[i][j][2 * p]);
                    atomicAdd(o + 1, wv * acc1[i][j][2 * p + 1]);
                }
            }
        }
    }
}

// ---------------------------------------------------------------------------
extern "C" void kernel_launch(void* const* d_in, const int* in_sizes, int n_in,
                              void* d_out, int out_size) {
    const float* x  = (const float*)d_in[0];
    const float* Wg = (const float*)d_in[1];
    const float* W1 = (const float*)d_in[2];
    const float* W2 = (const float*)d_in[3];
    const float* W3 = (const float*)d_in[4];
    float* out = (float*)d_out;

    static int attr_set = 0;
    if (!attr_set) {
        cudaFuncSetAttribute(moe_gemm<0>, cudaFuncAttributeMaxDynamicSharedMemorySize, NSS13 * 2 * ST13 + 1024);
        cudaFuncSetAttribute(moe_gemm<1>, cudaFuncAttributeMaxDynamicSharedMemorySize, NSS2 * 2 * ST2 + 1024);
        attr_set = 1;
    }

    zero_kernel<<<(NTOK * DIM + 1023) / 1024, 1024>>>(out);
    gate_kernel<<<(NTOK * 32 + 255) / 256, 256>>>(x, Wg);

    __half* w1h; cudaGetSymbolAddress((void**)&w1h, g_W1h);
    __half* w3h; cudaGetSymbolAddress((void**)&w3h, g_W3h);
    conv_kernel<<<1184, 256>>>(W1, w1h, NEXP * HID * DIM / 4);
    conv_kernel<<<1184, 256>>>(W3, w3h, NEXP * HID * DIM / 4);
    conv_pad_kernel<<<1184, 256>>>(W2);

    dim3 g13((HID + 127) / 128, MAXM / 128, NEXP);   // 22 x 32 x 8
    moe_gemm<0><<<g13, 512, NSS13 * 2 * ST13 + 1024>>>(nullptr);

    dim3 g2(DIM / 128, MAXM / 128, NEXP);            // 8 x 32 x 8
    moe_gemm<1><<<g2, 512, NSS2 * 2 * ST2 + 1024>>>(out);
}